// round 1
// baseline (speedup 1.0000x reference)
#include <cuda_runtime.h>
#include <math.h>

// ---------------------------------------------------------------------------
// PaddedSHCSA: out = softmax(mask(q@k^T / sqrt(F))) @ v,  qkv = x@W + b
// S=4096, F=2048, 3F=6144, n_padd read on-device (scalar int input).
// Round 0: fp32 SIMT tiled GEMMs (128x128x8, 256 thr, 8x8 microtile),
// scores materialized, softmax zero-fills masked region so att@v needs no mask.
// ---------------------------------------------------------------------------

#define S_MAX   4096
#define F3_MAX  6144

// scratch (static device arrays: allocation-free per harness rules)
__device__ float g_qkv[(size_t)S_MAX * F3_MAX];     // ~100.7 MB
__device__ float g_scores[(size_t)S_MAX * S_MAX];   // ~67 MB

// ---------------------------------------------------------------------------
// C[M,N] = A[M,K] @ B[K,N] (+bias), A,B,C row-major.
// skip_padded_rows: whole block row skipped if entirely < n_padd (output never read)
// causal_kmax:      kmax = min(K, blockRow0 + BM)   (att is 0 for j > i)
// pad_kmin:         kstart = floor(n_padd/BK)*BK    (att is 0 for j < n_padd)
// ---------------------------------------------------------------------------
__global__ __launch_bounds__(256) void gemm_nn_kernel(
    const float* __restrict__ A, int lda,
    const float* __restrict__ B, int ldb,
    const float* __restrict__ bias,
    float* __restrict__ C, int ldc,
    int K,
    const int* __restrict__ n_padd_ptr,
    int skip_padded_rows, int causal_kmax, int pad_kmin)
{
    const int BM = 128, BN = 128, BK = 8;
    const int m0 = blockIdx.y * BM;
    const int n0 = blockIdx.x * BN;
    const int np = n_padd_ptr ? *n_padd_ptr : 0;
    if (skip_padded_rows && (m0 + BM) <= np) return;
    const int kmax   = causal_kmax ? min(K, m0 + BM) : K;
    const int kstart = pad_kmin ? (np / BK) * BK : 0;

    __shared__ float As[BK][BM];
    __shared__ float Bs[BK][BN];

    const int tid = threadIdx.x;
    const int tx = tid & 15;        // 0..15
    const int ty = tid >> 4;        // 0..15
    const int arow = tid >> 1;      // 0..127
    const int acol = (tid & 1) * 4; // 0 or 4
    const int brow = tid >> 5;      // 0..7
    const int bcol = (tid & 31) * 4;

    float acc[8][8] = {};

    for (int k0 = kstart; k0 < kmax; k0 += BK) {
        float4 av = *reinterpret_cast<const float4*>(&A[(size_t)(m0 + arow) * lda + k0 + acol]);
        float4 bv = *reinterpret_cast<const float4*>(&B[(size_t)(k0 + brow) * ldb + n0 + bcol]);
        As[acol + 0][arow] = av.x;
        As[acol + 1][arow] = av.y;
        As[acol + 2][arow] = av.z;
        As[acol + 3][arow] = av.w;
        *reinterpret_cast<float4*>(&Bs[brow][bcol]) = bv;
        __syncthreads();
        #pragma unroll
        for (int k = 0; k < BK; k++) {
            float a[8], b[8];
            #pragma unroll
            for (int i = 0; i < 8; i++) a[i] = As[k][ty * 8 + i];
            #pragma unroll
            for (int j = 0; j < 8; j++) b[j] = Bs[k][tx * 8 + j];
            #pragma unroll
            for (int i = 0; i < 8; i++)
                #pragma unroll
                for (int j = 0; j < 8; j++) acc[i][j] += a[i] * b[j];
        }
        __syncthreads();
    }

    #pragma unroll
    for (int i = 0; i < 8; i++) {
        const int r = m0 + ty * 8 + i;
        #pragma unroll
        for (int j = 0; j < 8; j += 4) {
            const int c = n0 + tx * 8 + j;
            float4 v;
            v.x = acc[i][j + 0];
            v.y = acc[i][j + 1];
            v.z = acc[i][j + 2];
            v.w = acc[i][j + 3];
            if (bias) {
                v.x += bias[c + 0];
                v.y += bias[c + 1];
                v.z += bias[c + 2];
                v.w += bias[c + 3];
            }
            *reinterpret_cast<float4*>(&C[(size_t)r * ldc + c]) = v;
        }
    }
}

// ---------------------------------------------------------------------------
// scores[M,N] = scale * (A @ Bt^T);  A row i at A[i*lda], Bt row j at Bt[j*ldb]
// (both K-contiguous). Skips blocks entirely above the diagonal or entirely
// in the padded region (softmax never reads those).
// ---------------------------------------------------------------------------
__global__ __launch_bounds__(256) void gemm_nt_kernel(
    const float* __restrict__ A, int lda,
    const float* __restrict__ Bt, int ldb,
    float* __restrict__ C, int ldc,
    int K, float scale,
    const int* __restrict__ n_padd_ptr)
{
    const int BM = 128, BN = 128, BK = 8;
    const int m0 = blockIdx.y * BM;
    const int n0 = blockIdx.x * BN;
    if (n0 > m0 + BM - 1) return;            // above diagonal: never read
    const int np = *n_padd_ptr;
    if (m0 + BM <= np) return;               // fully padded rows: never read
    if (n0 + BN <= np) return;               // fully padded cols: never read

    __shared__ float As[BK][BM];
    __shared__ float Bs[BK][BN];

    const int tid = threadIdx.x;
    const int tx = tid & 15;
    const int ty = tid >> 4;
    const int arow = tid >> 1;
    const int acol = (tid & 1) * 4;

    float acc[8][8] = {};

    for (int k0 = 0; k0 < K; k0 += BK) {
        float4 av = *reinterpret_cast<const float4*>(&A [(size_t)(m0 + arow) * lda + k0 + acol]);
        float4 bv = *reinterpret_cast<const float4*>(&Bt[(size_t)(n0 + arow) * ldb + k0 + acol]);
        As[acol + 0][arow] = av.x;
        As[acol + 1][arow] = av.y;
        As[acol + 2][arow] = av.z;
        As[acol + 3][arow] = av.w;
        Bs[acol + 0][arow] = bv.x;
        Bs[acol + 1][arow] = bv.y;
        Bs[acol + 2][arow] = bv.z;
        Bs[acol + 3][arow] = bv.w;
        __syncthreads();
        #pragma unroll
        for (int k = 0; k < BK; k++) {
            float a[8], b[8];
            #pragma unroll
            for (int i = 0; i < 8; i++) a[i] = As[k][ty * 8 + i];
            #pragma unroll
            for (int j = 0; j < 8; j++) b[j] = Bs[k][tx * 8 + j];
            #pragma unroll
            for (int i = 0; i < 8; i++)
                #pragma unroll
                for (int j = 0; j < 8; j++) acc[i][j] += a[i] * b[j];
        }
        __syncthreads();
    }

    #pragma unroll
    for (int i = 0; i < 8; i++) {
        const int r = m0 + ty * 8 + i;
        #pragma unroll
        for (int j = 0; j < 8; j += 4) {
            const int c = n0 + tx * 8 + j;
            float4 v;
            v.x = acc[i][j + 0] * scale;
            v.y = acc[i][j + 1] * scale;
            v.z = acc[i][j + 2] * scale;
            v.w = acc[i][j + 3] * scale;
            *reinterpret_cast<float4*>(&C[(size_t)r * ldc + c]) = v;
        }
    }
}

// ---------------------------------------------------------------------------
// Row softmax over scores[i, np..i]; everything outside (and all of rows
// i < np) is written as exact 0, so att@v needs no masking.
// ---------------------------------------------------------------------------
__global__ __launch_bounds__(256) void softmax_kernel(
    float* __restrict__ s, int S, const int* __restrict__ n_padd_ptr)
{
    const int i = blockIdx.x;
    const int np = *n_padd_ptr;
    float* row = s + (size_t)i * S;
    const int tid = threadIdx.x;
    __shared__ float red[256];

    if (i < np) {
        for (int j = tid; j < S; j += 256) row[j] = 0.f;
        return;
    }

    // pass 1: max over [np, i]
    float m = -3.402823e38f;
    for (int j = np + tid; j <= i; j += 256) m = fmaxf(m, row[j]);
    red[tid] = m;
    __syncthreads();
    for (int off = 128; off > 0; off >>= 1) {
        if (tid < off) red[tid] = fmaxf(red[tid], red[tid + off]);
        __syncthreads();
    }
    m = red[0];
    __syncthreads();

    // pass 2: exp (stored in place) + sum
    float sum = 0.f;
    for (int j = np + tid; j <= i; j += 256) {
        float e = __expf(row[j] - m);
        row[j] = e;
        sum += e;
    }
    red[tid] = sum;
    __syncthreads();
    for (int off = 128; off > 0; off >>= 1) {
        if (tid < off) red[tid] += red[tid + off];
        __syncthreads();
    }
    const float inv = 1.f / red[0];
    __syncthreads();

    // pass 3: normalize valid region, zero-fill everything else
    for (int j = tid; j < S; j += 256) {
        float v = 0.f;
        if (j >= np && j <= i) v = row[j] * inv;
        row[j] = v;
    }
}

extern "C" void kernel_launch(void* const* d_in, const int* in_sizes, int n_in,
                              void* d_out, int out_size)
{
    const float* x  = (const float*)d_in[0];
    const float* W  = (const float*)d_in[1];
    const float* b  = (const float*)d_in[2];
    const int*   np = (const int*)  d_in[3];

    const int F3 = in_sizes[2];     // 6144
    const int F  = F3 / 3;          // 2048
    const int S  = in_sizes[0] / F; // 4096
    float* out = (float*)d_out;

    float* qkv = nullptr;
    float* sc  = nullptr;
    cudaGetSymbolAddress((void**)&qkv, g_qkv);
    cudaGetSymbolAddress((void**)&sc,  g_scores);

    const float scale = 1.0f / sqrtf((float)F);

    // 1) qkv = x @ W + b   [S, 3F]; skip block rows entirely < n_padd
    {
        dim3 grid(F3 / 128, S / 128);
        gemm_nn_kernel<<<grid, 256>>>(x, F, W, F3, b, qkv, F3, F,
                                      np, /*skip_rows=*/1, /*causal_k=*/0, /*pad_kmin=*/0);
    }
    // 2) scores = scale * q @ k^T  (causal/padding blocks skipped)
    {
        dim3 grid(S / 128, S / 128);
        gemm_nt_kernel<<<grid, 256>>>(qkv, F3, qkv + F, F3, sc, S, F, scale, np);
    }
    // 3) row softmax with zero-fill of masked region
    softmax_kernel<<<S, 256>>>(sc, S, np);

    // 4) out = att @ v; k bounded by causal structure and padding
    {
        dim3 grid(F / 128, S / 128);
        gemm_nn_kernel<<<grid, 256>>>(sc, S, qkv + 2 * F, F3, nullptr, out, F, S,
                                      np, /*skip_rows=*/0, /*causal_k=*/1, /*pad_kmin=*/1);
    }
}

// round 3
// speedup vs baseline: 2.6635x; 2.6635x over previous
#include <cuda_runtime.h>
#include <cuda_bf16.h>
#include <math.h>
#include <stdint.h>

// ============================================================================
// PaddedSHCSA via mma.sync bf16 (baseline PTX; tcgen05 unavailable at
// compute_103 target). All GEMMs split hi/lo bf16, 3-pass (AhBh+AhBl+AlBh)
// into fp32 accumulators -> ~1e-5 end-to-end error.
// ============================================================================

#define S_DIM   4096
#define F_DIM   2048
#define F3_DIM  6144

__device__ __nv_bfloat16 g_xh [(size_t)S_DIM * F_DIM];
__device__ __nv_bfloat16 g_xl [(size_t)S_DIM * F_DIM];
__device__ __nv_bfloat16 g_Wth[(size_t)F3_DIM * F_DIM];   // W^T [3F][F]
__device__ __nv_bfloat16 g_Wtl[(size_t)F3_DIM * F_DIM];
__device__ __nv_bfloat16 g_qh [(size_t)S_DIM * F_DIM];
__device__ __nv_bfloat16 g_ql [(size_t)S_DIM * F_DIM];
__device__ __nv_bfloat16 g_kh [(size_t)S_DIM * F_DIM];
__device__ __nv_bfloat16 g_kl [(size_t)S_DIM * F_DIM];
__device__ __nv_bfloat16 g_vTh[(size_t)F_DIM * S_DIM];    // v^T [F][S]
__device__ __nv_bfloat16 g_vTl[(size_t)F_DIM * S_DIM];
__device__ float         g_scores[(size_t)S_DIM * S_DIM];
__device__ __nv_bfloat16 g_atth[(size_t)S_DIM * S_DIM];
__device__ __nv_bfloat16 g_attl[(size_t)S_DIM * S_DIM];

// ---------------- low-level helpers -----------------------------------------
__device__ __forceinline__ uint32_t smem_u32(const void* p) {
    uint32_t a;
    asm("{ .reg .u64 t; cvta.to.shared.u64 t, %1; cvt.u32.u64 %0, t; }" : "=r"(a) : "l"(p));
    return a;
}
#define CP_ASYNC16(dst_u32, src_ptr) \
    asm volatile("cp.async.cg.shared.global [%0], [%1], 16;" :: "r"(dst_u32), "l"(src_ptr))
#define CP_COMMIT()  asm volatile("cp.async.commit_group;" ::: "memory")
#define CP_WAIT1()   asm volatile("cp.async.wait_group 1;" ::: "memory")

__device__ __forceinline__ void ldsm_x4(uint32_t* r, uint32_t addr) {
    asm volatile("ldmatrix.sync.aligned.m8n8.x4.shared.b16 {%0,%1,%2,%3}, [%4];"
        : "=r"(r[0]), "=r"(r[1]), "=r"(r[2]), "=r"(r[3]) : "r"(addr));
}
__device__ __forceinline__ void ldsm_x2(uint32_t* r, uint32_t addr) {
    asm volatile("ldmatrix.sync.aligned.m8n8.x2.shared.b16 {%0,%1}, [%2];"
        : "=r"(r[0]), "=r"(r[1]) : "r"(addr));
}
__device__ __forceinline__ void mma16816(float* c, const uint32_t* a, const uint32_t* b) {
    asm volatile("mma.sync.aligned.m16n8k16.row.col.f32.bf16.bf16.f32 "
        "{%0,%1,%2,%3}, {%4,%5,%6,%7}, {%8,%9}, {%0,%1,%2,%3};"
        : "+f"(c[0]), "+f"(c[1]), "+f"(c[2]), "+f"(c[3])
        : "r"(a[0]), "r"(a[1]), "r"(a[2]), "r"(a[3]), "r"(b[0]), "r"(b[1]));
}
__device__ __forceinline__ void split_bf16(float v, __nv_bfloat16& h, __nv_bfloat16& l) {
    h = __float2bfloat16(v);
    l = __float2bfloat16(v - __bfloat162float(h));
}

// ---------------- smem layout -----------------------------------------------
// pitch 40 halves (80 B) per 32-col row; tile = 128*80 = 10240 B
// stage s (0/1) at s*40960: Ah(+0) Al(+10240) Bh(+20480) Bl(+30720)
static constexpr int PA = 40;
static constexpr int TILE_B = 128 * PA * 2;         // 10240
static constexpr int STAGE_B = 4 * TILE_B;          // 40960
static constexpr int SMEM_BYTES = 2 * STAGE_B;      // 81920
static constexpr int PT = 136;                      // transpose staging pitch

// ============================================================================
// C[m0:+128, n0:+128] = sum_k A[m][k]*B[n][k]   (A,B K-major, hi/lo split)
// MODE 0: qkv (bias; epilogue -> q/k rows + vT transposed, all split h/l)
// MODE 1: scores (*scale -> fp32; causal/pad block skip)
// MODE 2: out (k range [np, m0+128); fp32 -> d_out; writes zeros if no work)
// ============================================================================
template<int MODE>
__global__ __launch_bounds__(256) void hmma_gemm(
    const __nv_bfloat16* __restrict__ Ah, const __nv_bfloat16* __restrict__ Al, int lda,
    const __nv_bfloat16* __restrict__ Bh, const __nv_bfloat16* __restrict__ Bl, int ldb,
    int K, const float* __restrict__ bias, float scale,
    float* __restrict__ outf, int ldo,
    __nv_bfloat16* __restrict__ qh, __nv_bfloat16* __restrict__ ql,
    __nv_bfloat16* __restrict__ kh, __nv_bfloat16* __restrict__ kl,
    __nv_bfloat16* __restrict__ vTh, __nv_bfloat16* __restrict__ vTl,
    int F, int S, const int* __restrict__ np_ptr)
{
    const int m0 = blockIdx.y * 128;
    const int n0 = blockIdx.x * 128;
    const int np = *np_ptr;

    if (MODE == 0) { if (m0 + 128 <= np) return; }
    if (MODE == 1) {
        if (n0 > m0) return;
        if (m0 + 128 <= np) return;
        if (n0 + 128 <= np) return;
    }

    int c0 = 0, c1 = K >> 5;
    if (MODE == 2) { c0 = np >> 5; c1 = (m0 + 128) >> 5; }
    const int nchunks = c1 - c0;

    extern __shared__ __align__(128) char smem[];
    const uint32_t sbase = smem_u32(smem);

    const int tid  = threadIdx.x;
    const int wid  = tid >> 5;
    const int lane = tid & 31;
    const int wm   = (wid >> 2) * 64;   // warp m offset
    const int wn   = (wid & 3) * 32;    // warp n offset

    float acc[4][4][4];
    #pragma unroll
    for (int i = 0; i < 4; i++)
        #pragma unroll
        for (int j = 0; j < 4; j++)
            #pragma unroll
            for (int e = 0; e < 4; e++) acc[i][j][e] = 0.f;

    // ---- prefetch helper (lambda) ----
    auto prefetch = [&](int c, int stage) {
        const int kc = c << 5;
        const uint32_t st = sbase + stage * STAGE_B;
        #pragma unroll
        for (int t = 0; t < 2; t++) {
            const int idx = tid + t * 256;          // 0..511
            const int r   = idx >> 2;               // 0..127
            const int seg = idx & 3;                // 16B segment
            const uint32_t d = (uint32_t)(r * PA * 2 + seg * 16);
            CP_ASYNC16(st + 0 * TILE_B + d, &Ah[(size_t)(m0 + r) * lda + kc + seg * 8]);
            CP_ASYNC16(st + 1 * TILE_B + d, &Al[(size_t)(m0 + r) * lda + kc + seg * 8]);
            CP_ASYNC16(st + 2 * TILE_B + d, &Bh[(size_t)(n0 + r) * ldb + kc + seg * 8]);
            CP_ASYNC16(st + 3 * TILE_B + d, &Bl[(size_t)(n0 + r) * ldb + kc + seg * 8]);
        }
    };

    if (nchunks > 0) {
        prefetch(c0, 0); CP_COMMIT();
        if (nchunks > 1) prefetch(c0 + 1, 1);
        CP_COMMIT();

        for (int i = 0; i < nchunks; i++) {
            CP_WAIT1();
            __syncthreads();
            const uint32_t st = sbase + (i & 1) * STAGE_B;
            const uint32_t aH = st + 0 * TILE_B, aL = st + 1 * TILE_B;
            const uint32_t bH = st + 2 * TILE_B, bL = st + 3 * TILE_B;

            #pragma unroll
            for (int ks = 0; ks < 2; ks++) {
                const int k0 = ks * 16;
                // B fragments: 4 n-tiles, hi & lo
                uint32_t bh[4][2], bl[4][2];
                const int brow = wn + (lane & 7);
                const int bcol = k0 + ((lane >> 3) & 1) * 8;
                #pragma unroll
                for (int nt = 0; nt < 4; nt++) {
                    const uint32_t off = (uint32_t)(((brow + nt * 8) * PA + bcol) * 2);
                    ldsm_x2(bh[nt], bH + off);
                    ldsm_x2(bl[nt], bL + off);
                }
                const int arow = wm + (lane & 15);
                const int acol = k0 + (lane >> 4) * 8;
                #pragma unroll
                for (int mt = 0; mt < 4; mt++) {
                    const uint32_t off = (uint32_t)(((arow + mt * 16) * PA + acol) * 2);
                    uint32_t a[4];
                    ldsm_x4(a, aH + off);
                    #pragma unroll
                    for (int nt = 0; nt < 4; nt++) mma16816(acc[mt][nt], a, bh[nt]);
                    #pragma unroll
                    for (int nt = 0; nt < 4; nt++) mma16816(acc[mt][nt], a, bl[nt]);
                    ldsm_x4(a, aL + off);
                    #pragma unroll
                    for (int nt = 0; nt < 4; nt++) mma16816(acc[mt][nt], a, bh[nt]);
                }
            }
            __syncthreads();
            if (i + 2 < nchunks) prefetch(c0 + i + 2, i & 1);
            CP_COMMIT();
        }
    }

    // ---------------- epilogue ----------------------------------------------
    const int mq = lane >> 2;           // 0..7
    const int nq = (lane & 3) * 2;      // 0,2,4,6

    if (MODE == 0) {
        const int region = n0 / F;      // 0=q 1=k 2=v
        if (region < 2) {
            __nv_bfloat16* Dh = region ? kh : ql - 0;   // placeholder fix below
            Dh = region ? kh : qh;
            __nv_bfloat16* Dl = region ? kl : ql;
            const int nb = n0 - region * F;
            #pragma unroll
            for (int mt = 0; mt < 4; mt++) {
                const int r0 = m0 + wm + mt * 16 + mq;
                #pragma unroll
                for (int nt = 0; nt < 4; nt++) {
                    const int nl = nb + wn + nt * 8 + nq;
                    const int gn = n0 + wn + nt * 8 + nq;
                    float v0 = acc[mt][nt][0] + bias[gn];
                    float v1 = acc[mt][nt][1] + bias[gn + 1];
                    float v2 = acc[mt][nt][2] + bias[gn];
                    float v3 = acc[mt][nt][3] + bias[gn + 1];
                    __nv_bfloat16 h0, l0, h1, l1;
                    split_bf16(v0, h0, l0); split_bf16(v1, h1, l1);
                    *(__nv_bfloat162*)&Dh[(size_t)r0 * F + nl] = __nv_bfloat162(h0, h1);
                    *(__nv_bfloat162*)&Dl[(size_t)r0 * F + nl] = __nv_bfloat162(l0, l1);
                    split_bf16(v2, h0, l0); split_bf16(v3, h1, l1);
                    *(__nv_bfloat162*)&Dh[(size_t)(r0 + 8) * F + nl] = __nv_bfloat162(h0, h1);
                    *(__nv_bfloat162*)&Dl[(size_t)(r0 + 8) * F + nl] = __nv_bfloat162(l0, l1);
                }
            }
        } else {
            // v region: stage transposed tile in smem, write vT coalesced
            __nv_bfloat16* smem_t = (__nv_bfloat16*)smem;
            const int vb = n0 - 2 * F;
            #pragma unroll
            for (int pass = 0; pass < 2; pass++) {
                __syncthreads();
                #pragma unroll
                for (int mt = 0; mt < 4; mt++) {
                    const int ml = wm + mt * 16 + mq;
                    #pragma unroll
                    for (int nt = 0; nt < 4; nt++) {
                        const int nl = wn + nt * 8 + nq;
                        const int gn = n0 + wn + nt * 8 + nq;
                        #pragma unroll
                        for (int e = 0; e < 4; e++) {
                            const int nn = nl + (e & 1);
                            const int mm = ml + (e >> 1) * 8;
                            float v = acc[mt][nt][e] + bias[gn + (e & 1)];
                            __nv_bfloat16 h = __float2bfloat16(v);
                            __nv_bfloat16 o = h;
                            if (pass) o = __float2bfloat16(v - __bfloat162float(h));
                            smem_t[nn * PT + mm] = o;
                        }
                    }
                }
                __syncthreads();
                __nv_bfloat16* D = pass ? vTl : vTh;
                const int r = tid >> 1;
                const int sg = (tid & 1) * 64;
                const uint4* src = (const uint4*)&smem_t[r * PT + sg];
                uint4* dst = (uint4*)&D[(size_t)(vb + r) * S + m0 + sg];
                #pragma unroll
                for (int j = 0; j < 8; j++) dst[j] = src[j];
            }
        }
    } else {
        const int ldc = ldo;
        #pragma unroll
        for (int mt = 0; mt < 4; mt++) {
            const int r0 = m0 + wm + mt * 16 + mq;
            #pragma unroll
            for (int nt = 0; nt < 4; nt++) {
                const int gn = n0 + wn + nt * 8 + nq;
                float2 p0, p1;
                p0.x = acc[mt][nt][0] * scale;  p0.y = acc[mt][nt][1] * scale;
                p1.x = acc[mt][nt][2] * scale;  p1.y = acc[mt][nt][3] * scale;
                *(float2*)&outf[(size_t)r0 * ldc + gn]       = p0;
                *(float2*)&outf[(size_t)(r0 + 8) * ldc + gn] = p1;
            }
        }
    }
}

// ---------------- fp32 -> bf16 hi/lo elementwise ----------------------------
__global__ __launch_bounds__(256) void split_convert_kernel(
    const float* __restrict__ in, __nv_bfloat16* __restrict__ h,
    __nv_bfloat16* __restrict__ l, size_t n4)
{
    for (size_t i = blockIdx.x * 256 + threadIdx.x; i < n4; i += (size_t)gridDim.x * 256) {
        float4 v = ((const float4*)in)[i];
        __nv_bfloat16 hh[4], ll[4];
        split_bf16(v.x, hh[0], ll[0]);
        split_bf16(v.y, hh[1], ll[1]);
        split_bf16(v.z, hh[2], ll[2]);
        split_bf16(v.w, hh[3], ll[3]);
        ((__nv_bfloat162*)h)[i * 2 + 0] = __nv_bfloat162(hh[0], hh[1]);
        ((__nv_bfloat162*)h)[i * 2 + 1] = __nv_bfloat162(hh[2], hh[3]);
        ((__nv_bfloat162*)l)[i * 2 + 0] = __nv_bfloat162(ll[0], ll[1]);
        ((__nv_bfloat162*)l)[i * 2 + 1] = __nv_bfloat162(ll[2], ll[3]);
    }
}

// ---------------- transpose + split: Wt[c][r] = W[r][c] ---------------------
__global__ __launch_bounds__(256) void transpose_split_kernel(
    const float* __restrict__ W, __nv_bfloat16* __restrict__ Th,
    __nv_bfloat16* __restrict__ Tl, int rows, int cols)
{
    __shared__ float tile[32][33];
    const int bx = blockIdx.x * 32;
    const int by = blockIdx.y * 32;
    const int tx = threadIdx.x & 31;
    const int ty = threadIdx.x >> 5;
    #pragma unroll
    for (int i = 0; i < 4; i++)
        tile[ty + i * 8][tx] = W[(size_t)(by + ty + i * 8) * cols + bx + tx];
    __syncthreads();
    #pragma unroll
    for (int i = 0; i < 4; i++) {
        const int orow = bx + ty + i * 8;
        const int ocol = by + tx;
        __nv_bfloat16 h, l;
        split_bf16(tile[tx][ty + i * 8], h, l);
        Th[(size_t)orow * rows + ocol] = h;
        Tl[(size_t)orow * rows + ocol] = l;
    }
}

// ---------------- softmax: fp32 scores -> att bf16 hi/lo --------------------
__global__ __launch_bounds__(256) void softmax_kernel(
    float* __restrict__ s, __nv_bfloat16* __restrict__ ah,
    __nv_bfloat16* __restrict__ al, int S, const int* __restrict__ np_ptr)
{
    const int i = blockIdx.x;
    const int np = *np_ptr;
    float* row = s + (size_t)i * S;
    __nv_bfloat16* rh = ah + (size_t)i * S;
    __nv_bfloat16* rl = al + (size_t)i * S;
    const int tid = threadIdx.x;
    __shared__ float red[256];

    if (i < np) {
        const __nv_bfloat16 z = __float2bfloat16(0.f);
        for (int j = tid; j < S; j += 256) { rh[j] = z; rl[j] = z; }
        return;
    }
    float m = -3.402823e38f;
    for (int j = np + tid; j <= i; j += 256) m = fmaxf(m, row[j]);
    red[tid] = m; __syncthreads();
    for (int off = 128; off > 0; off >>= 1) {
        if (tid < off) red[tid] = fmaxf(red[tid], red[tid + off]);
        __syncthreads();
    }
    m = red[0]; __syncthreads();

    float sum = 0.f;
    for (int j = np + tid; j <= i; j += 256) {
        float e = __expf(row[j] - m);
        row[j] = e;
        sum += e;
    }
    red[tid] = sum; __syncthreads();
    for (int off = 128; off > 0; off >>= 1) {
        if (tid < off) red[tid] += red[tid + off];
        __syncthreads();
    }
    const float inv = 1.f / red[0]; __syncthreads();

    for (int j = tid; j < S; j += 256) {
        float p = (j >= np && j <= i) ? row[j] * inv : 0.f;
        __nv_bfloat16 h, l;
        split_bf16(p, h, l);
        rh[j] = h; rl[j] = l;
    }
}

// ============================================================================
extern "C" void kernel_launch(void* const* d_in, const int* in_sizes, int n_in,
                              void* d_out, int out_size)
{
    const float* x  = (const float*)d_in[0];
    const float* W  = (const float*)d_in[1];
    const float* b  = (const float*)d_in[2];
    const int*   np = (const int*)  d_in[3];

    const int F3 = in_sizes[2];      // 6144
    const int F  = F3 / 3;           // 2048
    const int S  = in_sizes[0] / F;  // 4096
    float* out = (float*)d_out;

    __nv_bfloat16 *xh, *xl, *Wth, *Wtl, *qh, *ql, *kh, *kl, *vTh, *vTl, *atth, *attl;
    float* sc;
    cudaGetSymbolAddress((void**)&xh,  g_xh);   cudaGetSymbolAddress((void**)&xl,  g_xl);
    cudaGetSymbolAddress((void**)&Wth, g_Wth);  cudaGetSymbolAddress((void**)&Wtl, g_Wtl);
    cudaGetSymbolAddress((void**)&qh,  g_qh);   cudaGetSymbolAddress((void**)&ql,  g_ql);
    cudaGetSymbolAddress((void**)&kh,  g_kh);   cudaGetSymbolAddress((void**)&kl,  g_kl);
    cudaGetSymbolAddress((void**)&vTh, g_vTh);  cudaGetSymbolAddress((void**)&vTl, g_vTl);
    cudaGetSymbolAddress((void**)&sc,  g_scores);
    cudaGetSymbolAddress((void**)&atth, g_atth); cudaGetSymbolAddress((void**)&attl, g_attl);

    cudaFuncSetAttribute(hmma_gemm<0>, cudaFuncAttributeMaxDynamicSharedMemorySize, SMEM_BYTES);
    cudaFuncSetAttribute(hmma_gemm<1>, cudaFuncAttributeMaxDynamicSharedMemorySize, SMEM_BYTES);
    cudaFuncSetAttribute(hmma_gemm<2>, cudaFuncAttributeMaxDynamicSharedMemorySize, SMEM_BYTES);

    const float scale = 1.0f / sqrtf((float)F);

    split_convert_kernel<<<4096, 256>>>(x, xh, xl, (size_t)S * F / 4);
    transpose_split_kernel<<<dim3(F3 / 32, F / 32), 256>>>(W, Wth, Wtl, F, F3);

    // qkv = x@W + b  -> q/k rows + vT (split h/l)
    hmma_gemm<0><<<dim3(F3 / 128, S / 128), 256, SMEM_BYTES>>>(
        xh, xl, F, Wth, Wtl, F, F, b, 1.0f, nullptr, 0,
        qh, ql, kh, kl, vTh, vTl, F, S, np);

    // scores = scale * q@k^T
    hmma_gemm<1><<<dim3(S / 128, S / 128), 256, SMEM_BYTES>>>(
        qh, ql, F, kh, kl, F, F, nullptr, scale, sc, S,
        nullptr, nullptr, nullptr, nullptr, nullptr, nullptr, F, S, np);

    softmax_kernel<<<S, 256>>>(sc, atth, attl, S, np);

    // out = att@v
    hmma_gemm<2><<<dim3(F / 128, S / 128), 256, SMEM_BYTES>>>(
        atth, attl, S, vTh, vTl, S, S, nullptr, 1.0f, out, F,
        nullptr, nullptr, nullptr, nullptr, nullptr, nullptr, F, S, np);
}